// round 6
// baseline (speedup 1.0000x reference)
#include <cuda_runtime.h>

// ---------------------------------------------------------------------------
// ActorGCN: 2-layer GCN + two 105-way heads + gumbel softmax
// N=100000 nodes, E=1600000 edges, H=64, F_IN=14, heads 105+105
// ---------------------------------------------------------------------------

#define NN 100000
#define EE 1600000

typedef unsigned long long ull;

__device__ __forceinline__ ull pk2(float lo, float hi) {
    ull r; asm("mov.b64 %0, {%1, %2};" : "=l"(r) : "f"(lo), "f"(hi)); return r;
}
__device__ __forceinline__ void upk2(ull v, float& lo, float& hi) {
    asm("mov.b64 {%0, %1}, %2;" : "=f"(lo), "=f"(hi) : "l"(v));
}
__device__ __forceinline__ ull fma2(ull a, ull b, ull c) {
    ull d; asm("fma.rn.f32x2 %0, %1, %2, %3;" : "=l"(d) : "l"(a), "l"(b), "l"(c)); return d;
}

__device__ float g_bufA[NN * 64];
__device__ float g_bufB[NN * 64];
__device__ int   g_ecnt[NN];
__device__ float g_dinv[NN];
__device__ float g_stem[NN];
__device__ int   g_off[NN + 1];
__device__ int   g_cur[NN];
__device__ int   g_srcs[EE];
__device__ float g_ew[EE];
__device__ int   g_csum[1024];
__device__ int   g_coff[1024];
__device__ int   g_is64;

__global__ void k_probe(const int* __restrict__ ei32) {
    __shared__ int nonzero;
    if (threadIdx.x == 0) nonzero = 0;
    __syncthreads();
    for (int i = threadIdx.x; i < 1024; i += 256) {
        if (ei32[2 * i + 1] != 0) nonzero = 1;
    }
    __syncthreads();
    if (threadIdx.x == 0) g_is64 = nonzero ? 0 : 1;
}

__device__ __forceinline__ int idx_at(const void* p, long long i) {
    return g_is64 ? (int)((const long long*)p)[i] : ((const int*)p)[i];
}

__global__ void k_init(int n) {
    int i = blockIdx.x * blockDim.x + threadIdx.x;
    if (i < n) { g_ecnt[i] = 0; g_stem[i] = 0.f; }
}

__global__ void k_stem(const void* __restrict__ si, int s) {
    int i = blockIdx.x * blockDim.x + threadIdx.x;
    if (i < s) {
        int v = idx_at(si, i);
        if (v >= 0 && v < NN) g_stem[v] = 1.0f;
    }
}

__global__ void k_hist(const void* __restrict__ ei, int e) {
    int i = (blockIdx.x * blockDim.x + threadIdx.x) * 2;
    if (i >= e) return;
    if (g_is64) {
        const long long* dst = (const long long*)ei + e;
        if (i + 1 < e && ((((unsigned long long)(dst + i)) & 15) == 0)) {
            longlong2 v = *(const longlong2*)(dst + i);
            int d0 = (int)v.x, d1 = (int)v.y;
            if (d0 >= 0 && d0 < NN) atomicAdd(&g_ecnt[d0], 1);
            if (d1 >= 0 && d1 < NN) atomicAdd(&g_ecnt[d1], 1);
        } else {
            for (int k = i; k < min(e, i + 2); k++) {
                int d = (int)dst[k];
                if (d >= 0 && d < NN) atomicAdd(&g_ecnt[d], 1);
            }
        }
    } else {
        const int* dst = (const int*)ei + e;
        for (int k = i; k < min(e, i + 2); k++) {
            int d = dst[k];
            if (d >= 0 && d < NN) atomicAdd(&g_ecnt[d], 1);
        }
    }
}

__global__ void k_chunksum(int n) {
    int c = blockIdx.x * blockDim.x + threadIdx.x;   // 0..1023
    int ch = (n + 1023) >> 10;
    int beg = c * ch, end = min(n, beg + ch);
    int sum = 0;
    for (int i = beg; i < end; i++) sum += g_ecnt[i];
    g_csum[c] = sum;
}

__global__ void k_scan() {
    __shared__ int sh[1024];
    int t = threadIdx.x;
    int v = g_csum[t];
    sh[t] = v; __syncthreads();
    for (int off = 1; off < 1024; off <<= 1) {
        int add = (t >= off) ? sh[t - off] : 0;
        __syncthreads();
        sh[t] += add;
        __syncthreads();
    }
    g_coff[t] = sh[t] - v;  // exclusive
}

__global__ void k_offsets(int n, int e) {
    int c = blockIdx.x * blockDim.x + threadIdx.x;   // 0..1023
    int ch = (n + 1023) >> 10;
    int beg = c * ch, end = min(n, beg + ch);
    if (beg > n) beg = n;
    int run = g_coff[c];
    for (int i = beg; i < end; i++) {
        g_off[i] = run;
        g_cur[i] = run;
        int d = g_ecnt[i];
        g_dinv[i] = rsqrtf((float)(d + 1));   // +1 self-loop
        run += d;
    }
    if (c == 0) g_off[n] = e;
}

__global__ void k_scatter(const void* __restrict__ ei, int e) {
    int i = blockIdx.x * blockDim.x + threadIdx.x;
    if (i < e) {
        int s = idx_at(ei, i);
        int d = idx_at(ei, (long long)e + i);
        if (s >= 0 && s < NN && d >= 0 && d < NN) {
            int p = atomicAdd(&g_cur[d], 1);
            if (p >= 0 && p < EE) {
                g_srcs[p] = s;
                g_ew[p]   = g_dinv[s];
            }
        }
    }
}

// xw1 = [x | stem] @ W1 (15 x 64)
__global__ void k_xw1(const float* __restrict__ x, const float* __restrict__ W1, int n) {
    __shared__ float sW[15 * 64];
    __shared__ float sx[4][15];
    int tx = threadIdx.x, ty = threadIdx.y;
    int tid = ty * 64 + tx;
    for (int idx = tid; idx < 15 * 64; idx += 256) sW[idx] = W1[idx];
    int node = blockIdx.x * 4 + ty;
    if (tx < 15 && node < n) sx[ty][tx] = (tx < 14) ? x[node * 14 + tx] : g_stem[node];
    __syncthreads();
    if (node < n) {
        float acc = 0.f;
        #pragma unroll
        for (int k = 0; k < 15; k++) acc += sx[ty][k] * sW[k * 64 + tx];
        g_bufA[node * 64 + tx] = acc;
    }
}

// Pull aggregation with smem staging, f32x2 FMA, unroll x8.
__global__ void k_agg(const float* __restrict__ bias, const float* __restrict__ drop, int n) {
    __shared__ int   s_idx[8][32];
    __shared__ float s_w[8][32];
    int wrp = threadIdx.x >> 5, lane = threadIdx.x & 31;
    int node = blockIdx.x * 8 + wrp;
    if (node >= n) return;
    const ull* __restrict__ in2 = (const ull*)g_bufA;
    float di = g_dinv[node];
    float sx, sy;
    upk2(in2[node * 32 + lane], sx, sy);
    ull acc = pk2(di * sx, di * sy);
    int beg = g_off[node], end = g_off[node + 1];
    for (int base = beg; base < end; base += 32) {
        int m = min(32, end - base);
        if (lane < m) {
            s_idx[wrp][lane] = g_srcs[base + lane];
            s_w[wrp][lane]   = g_ew[base + lane];
        }
        __syncwarp();
        int j = 0;
        for (; j + 8 <= m; j += 8) {
            ull v0 = in2[s_idx[wrp][j    ] * 32 + lane];
            ull v1 = in2[s_idx[wrp][j + 1] * 32 + lane];
            ull v2 = in2[s_idx[wrp][j + 2] * 32 + lane];
            ull v3 = in2[s_idx[wrp][j + 3] * 32 + lane];
            ull v4 = in2[s_idx[wrp][j + 4] * 32 + lane];
            ull v5 = in2[s_idx[wrp][j + 5] * 32 + lane];
            ull v6 = in2[s_idx[wrp][j + 6] * 32 + lane];
            ull v7 = in2[s_idx[wrp][j + 7] * 32 + lane];
            acc = fma2(v0, pk2(s_w[wrp][j    ], s_w[wrp][j    ]), acc);
            acc = fma2(v1, pk2(s_w[wrp][j + 1], s_w[wrp][j + 1]), acc);
            acc = fma2(v2, pk2(s_w[wrp][j + 2], s_w[wrp][j + 2]), acc);
            acc = fma2(v3, pk2(s_w[wrp][j + 3], s_w[wrp][j + 3]), acc);
            acc = fma2(v4, pk2(s_w[wrp][j + 4], s_w[wrp][j + 4]), acc);
            acc = fma2(v5, pk2(s_w[wrp][j + 5], s_w[wrp][j + 5]), acc);
            acc = fma2(v6, pk2(s_w[wrp][j + 6], s_w[wrp][j + 6]), acc);
            acc = fma2(v7, pk2(s_w[wrp][j + 7], s_w[wrp][j + 7]), acc);
        }
        for (; j < m; j++) {
            ull v = in2[s_idx[wrp][j] * 32 + lane];
            float w = s_w[wrp][j];
            acc = fma2(v, pk2(w, w), acc);
        }
        __syncwarp();
    }
    float ax, ay;
    upk2(acc, ax, ay);
    float2 bv = ((const float2*)bias)[lane];
    float2 dv = ((const float2*)drop)[(size_t)node * 32 + lane];
    float o0 = fmaxf(fmaf(di, ax, bv.x), 0.f) * dv.x;
    float o1 = fmaxf(fmaf(di, ay, bv.y), 0.f) * dv.y;
    ((float2*)g_bufB)[node * 32 + lane] = make_float2(o0, o1);
}

// bufA = bufB @ W2 (64x64). 64 threads, BM=64 nodes, 8x8 microtile, f32x2.
__global__ void k_gemm64(const float* __restrict__ W, int n) {
    __shared__ float Ash[64 * 65];
    __shared__ float Wsh[64 * 64];
    int tid = threadIdx.x;        // 64 threads
    int base = blockIdx.x * 64;
    for (int idx = tid; idx < 4096; idx += 64) Wsh[idx] = W[idx];
    for (int idx = tid; idx < 4096; idx += 64) {
        int nl = idx >> 6, k = idx & 63;
        int node = base + nl;
        Ash[nl * 65 + k] = (node < n) ? g_bufB[node * 64 + k] : 0.f;
    }
    __syncthreads();
    int tx = tid & 7, ty = tid >> 3;
    ull acc[8][4];
    #pragma unroll
    for (int r = 0; r < 8; r++)
        #pragma unroll
        for (int c = 0; c < 4; c++) acc[r][c] = 0ull;
    #pragma unroll 4
    for (int k = 0; k < 64; k++) {
        const ull* wrow = (const ull*)&Wsh[k * 64 + tx * 8];
        ull w0 = wrow[0], w1 = wrow[1], w2 = wrow[2], w3 = wrow[3];
        #pragma unroll
        for (int r = 0; r < 8; r++) {
            float a = Ash[(ty * 8 + r) * 65 + k];
            ull a2 = pk2(a, a);
            acc[r][0] = fma2(a2, w0, acc[r][0]);
            acc[r][1] = fma2(a2, w1, acc[r][1]);
            acc[r][2] = fma2(a2, w2, acc[r][2]);
            acc[r][3] = fma2(a2, w3, acc[r][3]);
        }
    }
    #pragma unroll
    for (int r = 0; r < 8; r++) {
        int node = base + ty * 8 + r;
        if (node < n) {
            ull* out = (ull*)&g_bufA[node * 64 + tx * 8];
            out[0] = acc[r][0]; out[1] = acc[r][1];
            out[2] = acc[r][2]; out[3] = acc[r][3];
        }
    }
}

// Fused heads GEMM + bias + logits store + TWO independent gumbel softmaxes
// (block head: cols 0..104, stem head: cols 105..209; cols 210..223 padding).
// BM=64 nodes, 224 threads: tx=0..27 (8 cols each), ty=0..7 (8 rows each).
// Dynamic smem: Wsh[64*224] | Ash[64*65] | redB[64*28] | redS[64*28] | bias_s[224]
__global__ void k_heads_sm(const float* __restrict__ Wb, const float* __restrict__ bbv,
                           const float* __restrict__ Wst, const float* __restrict__ bsv,
                           const float* __restrict__ gbv, const float* __restrict__ gsv,
                           float* __restrict__ outB, float* __restrict__ outS,
                           float* __restrict__ selB, float* __restrict__ selS, int n) {
    extern __shared__ float sm[];
    float* Wsh    = sm;                              // 14336
    float* Ash    = sm + 14336;                      // 4160
    float* redB   = sm + 14336 + 4160;               // 1792
    float* redS   = sm + 14336 + 4160 + 1792;        // 1792
    float* bias_s = sm + 14336 + 4160 + 1792 + 1792; // 224
    int tid = threadIdx.x;                           // 224 threads
    int base = blockIdx.x * 64;

    bias_s[tid] = (tid < 105) ? bbv[tid] : (tid < 210 ? bsv[tid - 105] : 0.f);
    {
        int col = tid;
        float v;
        for (int k = 0; k < 64; k++) {
            if (col < 105)      v = Wb[k * 105 + col];
            else if (col < 210) v = Wst[k * 105 + col - 105];
            else                v = 0.f;
            Wsh[k * 224 + col] = v;
        }
    }
    for (int idx = tid; idx < 4096; idx += 224) {
        int nl = idx >> 6, k = idx & 63;
        int node = base + nl;
        Ash[nl * 65 + k] = (node < n) ? g_bufB[node * 64 + k] : 0.f;
    }
    __syncthreads();

    int tx = tid % 28, ty = tid / 28;   // col group (8 cols), row group (8 rows)
    ull acc[8][4];
    #pragma unroll
    for (int r = 0; r < 8; r++)
        #pragma unroll
        for (int c = 0; c < 4; c++) acc[r][c] = 0ull;
    #pragma unroll 2
    for (int k = 0; k < 64; k++) {
        const ull* wrow = (const ull*)&Wsh[k * 224 + tx * 8];
        ull w0 = wrow[0], w1 = wrow[1], w2 = wrow[2], w3 = wrow[3];
        #pragma unroll
        for (int r = 0; r < 8; r++) {
            float a = Ash[(ty * 8 + r) * 65 + k];
            ull a2 = pk2(a, a);
            acc[r][0] = fma2(a2, w0, acc[r][0]);
            acc[r][1] = fma2(a2, w1, acc[r][1]);
            acc[r][2] = fma2(a2, w2, acc[r][2]);
            acc[r][3] = fma2(a2, w3, acc[r][3]);
        }
    }

    // Per row: add bias, store logits, add gumbel -> z (packed in acc),
    // per-head local maxes.
    #pragma unroll
    for (int r = 0; r < 8; r++) {
        int node = base + ty * 8 + r;
        bool live = (node < n);
        float lmB = -1e30f, lmS = -1e30f;
        #pragma unroll
        for (int c2 = 0; c2 < 4; c2++) {
            float p0, p1;
            upk2(acc[r][c2], p0, p1);
            int col0 = tx * 8 + c2 * 2;
            int col1 = col0 + 1;
            float v0 = p0 + bias_s[col0];
            float v1 = p1 + bias_s[col1];
            float z0 = -1e30f, z1 = -1e30f;
            if (live) {
                if (col0 < 105) {
                    outB[(size_t)node * 105 + col0] = v0;
                    z0 = v0 + gbv[(size_t)node * 105 + col0];
                    lmB = fmaxf(lmB, z0);
                } else if (col0 < 210) {
                    outS[(size_t)node * 105 + col0 - 105] = v0;
                    z0 = v0 + gsv[(size_t)node * 105 + col0 - 105];
                    lmS = fmaxf(lmS, z0);
                }
                if (col1 < 105) {
                    outB[(size_t)node * 105 + col1] = v1;
                    z1 = v1 + gbv[(size_t)node * 105 + col1];
                    lmB = fmaxf(lmB, z1);
                } else if (col1 < 210) {
                    outS[(size_t)node * 105 + col1 - 105] = v1;
                    z1 = v1 + gsv[(size_t)node * 105 + col1 - 105];
                    lmS = fmaxf(lmS, z1);
                }
            }
            acc[r][c2] = pk2(z0, z1);
        }
        redB[(ty * 8 + r) * 28 + tx] = lmB;
        redS[(ty * 8 + r) * 28 + tx] = lmS;
    }
    __syncthreads();
    float mB[8], mS[8];
    #pragma unroll
    for (int r = 0; r < 8; r++) {
        const float* rowB = &redB[(ty * 8 + r) * 28];
        const float* rowS = &redS[(ty * 8 + r) * 28];
        float a = rowB[0], b = rowS[0];
        #pragma unroll
        for (int t = 1; t < 28; t++) { a = fmaxf(a, rowB[t]); b = fmaxf(b, rowS[t]); }
        mB[r] = a; mS[r] = b;
    }
    __syncthreads();
    // exp with per-head max + per-head local sums
    #pragma unroll
    for (int r = 0; r < 8; r++) {
        float sB = 0.f, sS = 0.f;
        #pragma unroll
        for (int c2 = 0; c2 < 4; c2++) {
            float z0, z1;
            upk2(acc[r][c2], z0, z1);
            int col0 = tx * 8 + c2 * 2;
            int col1 = col0 + 1;
            float e0 = 0.f, e1 = 0.f;
            if (z0 > -1e29f) {
                if (col0 < 105) { e0 = __expf(z0 - mB[r]); sB += e0; }
                else            { e0 = __expf(z0 - mS[r]); sS += e0; }
            }
            if (z1 > -1e29f) {
                if (col1 < 105) { e1 = __expf(z1 - mB[r]); sB += e1; }
                else            { e1 = __expf(z1 - mS[r]); sS += e1; }
            }
            acc[r][c2] = pk2(e0, e1);
        }
        redB[(ty * 8 + r) * 28 + tx] = sB;
        redS[(ty * 8 + r) * 28 + tx] = sS;
    }
    __syncthreads();
    #pragma unroll
    for (int r = 0; r < 8; r++) {
        int node = base + ty * 8 + r;
        if (node >= n) continue;
        const float* rowB = &redB[(ty * 8 + r) * 28];
        const float* rowS = &redS[(ty * 8 + r) * 28];
        float ssB = 0.f, ssS = 0.f;
        #pragma unroll
        for (int t = 0; t < 28; t++) { ssB += rowB[t]; ssS += rowS[t]; }
        float invB = 1.0f / ssB;
        float invS = 1.0f / ssS;
        #pragma unroll
        for (int c2 = 0; c2 < 4; c2++) {
            float e0, e1;
            upk2(acc[r][c2], e0, e1);
            int col0 = tx * 8 + c2 * 2;
            int col1 = col0 + 1;
            if (col0 < 105)      selB[(size_t)node * 105 + col0] = e0 * invB;
            else if (col0 < 210) selS[(size_t)node * 105 + col0 - 105] = e0 * invS;
            if (col1 < 105)      selB[(size_t)node * 105 + col1] = e1 * invB;
            else if (col1 < 210) selS[(size_t)node * 105 + col1 - 105] = e1 * invS;
        }
    }
}

extern "C" void kernel_launch(void* const* d_in, const int* in_sizes, int n_in,
                              void* d_out, int out_size) {
    const float* x   = (const float*)d_in[0];
    const float* W1  = (const float*)d_in[1];
    const float* b1  = (const float*)d_in[2];
    const float* W2  = (const float*)d_in[3];
    const float* b2  = (const float*)d_in[4];
    const float* Wb  = (const float*)d_in[5];
    const float* bb  = (const float*)d_in[6];
    const float* Ws  = (const float*)d_in[7];
    const float* bs  = (const float*)d_in[8];
    const float* dr1 = (const float*)d_in[9];
    const float* dr2 = (const float*)d_in[10];
    const float* gb  = (const float*)d_in[11];
    const float* gs  = (const float*)d_in[12];
    const void*  ei  = d_in[13];
    const void*  si  = d_in[14];

    int n = in_sizes[0] / 14;
    int e = in_sizes[13] / 2;
    int s = in_sizes[14];

    float* out = (float*)d_out;
    size_t NH = (size_t)n * 105;
    float* outB = out;
    float* outS = out + NH;
    float* selB = out + 2 * NH;
    float* selS = out + 3 * NH;

    static int smem_set = 0;
    int smem_bytes = (14336 + 4160 + 1792 + 1792 + 224) * 4;  // 89216
    if (!smem_set) {
        cudaFuncSetAttribute(k_heads_sm, cudaFuncAttributeMaxDynamicSharedMemorySize, smem_bytes);
        smem_set = 1;
    }

    k_probe   <<<1, 256>>>((const int*)ei);
    k_init    <<<(n + 255) / 256, 256>>>(n);
    k_stem    <<<(s + 255) / 256, 256>>>(si, s);
    k_hist    <<<(e / 2 + 255) / 256, 256>>>(ei, e);
    k_chunksum<<<4, 256>>>(n);
    k_scan    <<<1, 1024>>>();
    k_offsets <<<4, 256>>>(n, e);
    k_scatter <<<(e + 255) / 256, 256>>>(ei, e);
    k_xw1     <<<(n + 3) / 4, dim3(64, 4)>>>(x, W1, n);
    k_agg     <<<(n + 7) / 8, 256>>>(b1, dr1, n);
    k_gemm64  <<<(n + 63) / 64, 64>>>(W2, n);
    k_agg     <<<(n + 7) / 8, 256>>>(b2, dr2, n);
    k_heads_sm<<<(n + 63) / 64, 224, smem_bytes>>>(Wb, bb, Ws, bs, gb, gs,
                                                   outB, outS, selB, selS, n);
}